// round 14
// baseline (speedup 1.0000x reference)
#include <cuda_runtime.h>
#include <cuda_fp16.h>
#include <math.h>
#include <stdint.h>

#define MROWS 8192           // B*T = 4*2048
#define CDIM  768
#define TSEQ  2048
#define NBATCH 4
#define NHEAD 12
#define HD    64

// ---------------- scratch (no allocations allowed) ----------------
__device__ __half g_ln [(size_t)MROWS * CDIM];
__device__ __half g_qkv[(size_t)MROWS * 3 * CDIM];
__device__ __half g_att[(size_t)MROWS * CDIM];
__device__ float  g_x1 [(size_t)MROWS * CDIM];
__device__ __half g_fc [(size_t)MROWS * 4 * CDIM];

#define W_QKV_N (768*2304)
#define W_PROJ_N (768*768)
#define W_FC_N (768*3072)
#define W_MP_N (3072*768)
__device__ __half g_w[W_QKV_N + W_PROJ_N + W_FC_N + W_MP_N];

// softmax scale folded into q at qkv epilogue: 0.125 * log2(e)
#define QSCALE 0.18033688011112042f

// ---------------- helpers ----------------
__device__ __forceinline__ float warp_sum(float v) {
#pragma unroll
    for (int m = 16; m; m >>= 1) v += __shfl_xor_sync(0xffffffffu, v, m);
    return v;
}

__device__ __forceinline__ float fast_ex2(float x) {
    float y;
    asm("ex2.approx.ftz.f32 %0, %1;" : "=f"(y) : "f"(x));
    return y;
}
__device__ __forceinline__ float fast_rcp(float x) {
    float y;
    asm("rcp.approx.ftz.f32 %0, %1;" : "=f"(y) : "f"(x));
    return y;
}

__device__ __forceinline__ float gelu_tanh(float x) {
    const float c = 0.7978845608028654f;  // sqrt(2/pi)
    float u = c * (x + 0.044715f * x * x * x);
    float t = fast_ex2(2.885390081777927f * u);   // exp(2u)
    float th = 1.0f - 2.0f * fast_rcp(t + 1.0f);
    return 0.5f * x * (1.0f + th);
}

__device__ __forceinline__ uint32_t smem_u32(const void* p) {
    return (uint32_t)__cvta_generic_to_shared(p);
}

__device__ __forceinline__ void cp16(uint32_t dst, const void* src) {
    asm volatile("cp.async.cg.shared.global [%0], [%1], 16;\n" :: "r"(dst), "l"(src));
}
__device__ __forceinline__ void cp_commit() { asm volatile("cp.async.commit_group;\n"); }
template<int N> __device__ __forceinline__ void cp_wait() {
    asm volatile("cp.async.wait_group %0;\n" :: "n"(N));
}

__device__ __forceinline__ void ldsm_x4(uint32_t (&r)[4], uint32_t addr) {
    asm volatile("ldmatrix.sync.aligned.m8n8.x4.shared.b16 {%0,%1,%2,%3}, [%4];"
        : "=r"(r[0]), "=r"(r[1]), "=r"(r[2]), "=r"(r[3]) : "r"(addr));
}
__device__ __forceinline__ void ldsm_x4t(uint32_t (&r)[4], uint32_t addr) {
    asm volatile("ldmatrix.sync.aligned.m8n8.x4.trans.shared.b16 {%0,%1,%2,%3}, [%4];"
        : "=r"(r[0]), "=r"(r[1]), "=r"(r[2]), "=r"(r[3]) : "r"(addr));
}
__device__ __forceinline__ void mma16816(float (&d)[4], const uint32_t (&a)[4],
                                         const uint32_t (&b)[2]) {
    asm volatile(
        "mma.sync.aligned.m16n8k16.row.col.f32.f16.f16.f32 "
        "{%0,%1,%2,%3},{%4,%5,%6,%7},{%8,%9},{%0,%1,%2,%3};"
        : "+f"(d[0]), "+f"(d[1]), "+f"(d[2]), "+f"(d[3])
        : "r"(a[0]), "r"(a[1]), "r"(a[2]), "r"(a[3]), "r"(b[0]), "r"(b[1]));
}

__device__ __forceinline__ uint32_t packh(float a, float b) {
    __half2 h = __floats2half2_rn(a, b);
    return *(uint32_t*)&h;
}

// ---------------- fused weight convert f32 -> fp16 (one launch) ------
#define N4_QKV (W_QKV_N / 4)
#define N4_PROJ (W_PROJ_N / 4)
#define N4_FC (W_FC_N / 4)
#define N4_MP (W_MP_N / 4)
#define N4_TOTAL (N4_QKV + N4_PROJ + N4_FC + N4_MP)

__global__ __launch_bounds__(256) void cvt_all_kernel(
    const float4* __restrict__ w0, const float4* __restrict__ w1,
    const float4* __restrict__ w2, const float4* __restrict__ w3,
    uint32_t* __restrict__ h)
{
    int i = blockIdx.x * 256 + threadIdx.x;
    if (i >= N4_TOTAL) return;
    const float4* src;
    int j = i;
    if (j < N4_QKV) { src = w0; }
    else if ((j -= N4_QKV) < N4_PROJ) { src = w1; }
    else if ((j -= N4_PROJ) < N4_FC) { src = w2; }
    else { j -= N4_FC; src = w3; }
    float4 v = src[j];
    h[2 * i]     = packh(v.x, v.y);
    h[2 * i + 1] = packh(v.z, v.w);
}

// ---------------- LayerNorm (row = 768, ddof=1) -> fp16 --------
__global__ __launch_bounds__(256) void ln_kernel(
    const float* __restrict__ x, const float* __restrict__ w,
    const float* __restrict__ b, __half* __restrict__ y)
{
    const int row = blockIdx.x;
    const float* xr = x + (size_t)row * CDIM;
    const int t = threadIdx.x;

    float v0 = xr[t], v1 = xr[t + 256], v2 = xr[t + 512];
    float s  = v0 + v1 + v2;
    float s2 = v0 * v0 + v1 * v1 + v2 * v2;

    __shared__ float sh[2][8];
    s = warp_sum(s); s2 = warp_sum(s2);
    int wid = t >> 5, lane = t & 31;
    if (lane == 0) { sh[0][wid] = s; sh[1][wid] = s2; }
    __syncthreads();
    if (wid == 0) {
        float a = (lane < 8) ? sh[0][lane] : 0.0f;
        float c = (lane < 8) ? sh[1][lane] : 0.0f;
        a = warp_sum(a); c = warp_sum(c);
        if (lane == 0) { sh[0][0] = a; sh[1][0] = c; }
    }
    __syncthreads();
    s = sh[0][0]; s2 = sh[1][0];

    float mean = s * (1.0f / (float)CDIM);
    float var  = (s2 - (float)CDIM * mean * mean) * (1.0f / (float)(CDIM - 1));
    float rstd = rsqrtf(var + 1e-5f);

    size_t base = (size_t)row * CDIM;
#pragma unroll
    for (int j = 0; j < 3; j++) {
        int c = t + j * 256;
        float v = (j == 0 ? v0 : (j == 1 ? v1 : v2));
        y[base + c] = __float2half_rn((v - mean) * rstd * w[c] + b[c]);
    }
}

// ---------------- fp16 tensor-core GEMM, 128x128x32 ----------------
#define GEMM_SMEM_ELEMS ((2*128*40) + (2*32*136))
#define GEMM_SMEM_BYTES (GEMM_SMEM_ELEMS * 2)

template<int EPI, bool STOREF, bool STOREH, bool SCALEQ>
__global__ __launch_bounds__(256, 2) void hgemm(
    int M, int N, int K,
    const __half* __restrict__ A, const __half* __restrict__ B,
    const float* __restrict__ bias, const float* __restrict__ Res,
    float* __restrict__ C, __half* __restrict__ Ch)
{
    extern __shared__ __half sm[];
    __half* sA = sm;                    // [2][128][40]
    __half* sB = sA + 2 * 128 * 40;     // [2][32][136]
    const uint32_t uA = smem_u32(sA), uB = smem_u32(sB);

    const int tid  = threadIdx.x;
    const int warp = tid >> 5, lane = tid & 31;
    const int wr = warp >> 1, wc = warp & 1;
    const int bm = blockIdx.y * 128, bn = blockIdx.x * 128;

    float acc[2][8][4];
#pragma unroll
    for (int i = 0; i < 2; i++)
#pragma unroll
        for (int j = 0; j < 8; j++)
#pragma unroll
            for (int k = 0; k < 4; k++) acc[i][j][k] = 0.0f;

    auto load_tile = [&](int kt, int buf) {
#pragma unroll
        for (int i = 0; i < 2; i++) {
            int id = tid + i * 256;
            int r = id >> 2, c = id & 3;
            uint32_t off = (uint32_t)((buf * 128 + r) * 40 + c * 8) * 2;
            cp16(uA + off, A + (size_t)(bm + r) * K + kt * 32 + c * 8);
        }
#pragma unroll
        for (int i = 0; i < 2; i++) {
            int id = tid + i * 256;
            int r = id >> 4, c = id & 15;
            uint32_t off = (uint32_t)((buf * 32 + r) * 136 + c * 8) * 2;
            cp16(uB + off, B + (size_t)(kt * 32 + r) * N + bn + c * 8);
        }
    };

    const int KT = K >> 5;
    load_tile(0, 0);
    cp_commit();

    for (int kt = 0; kt < KT; ++kt) {
        const int buf = kt & 1;
        if (kt + 1 < KT) {
            load_tile(kt + 1, buf ^ 1);
            cp_commit();
            cp_wait<1>();
        } else {
            cp_wait<0>();
        }
        __syncthreads();

#pragma unroll
        for (int ks = 0; ks < 2; ++ks) {
            uint32_t a[2][4], b[8][2];
#pragma unroll
            for (int ti = 0; ti < 2; ++ti) {
                int r = wr * 32 + ti * 16 + (lane & 15);
                int col = ks * 16 + (lane >> 4) * 8;
                ldsm_x4(a[ti], uA + (uint32_t)((buf * 128 + r) * 40 + col) * 2);
            }
#pragma unroll
            for (int p = 0; p < 4; ++p) {
                int kr = ks * 16 + (lane & 15);
                int col = wc * 64 + p * 16 + (lane >> 4) * 8;
                uint32_t r4[4];
                ldsm_x4t(r4, uB + (uint32_t)((buf * 32 + kr) * 136 + col) * 2);
                b[2 * p][0] = r4[0]; b[2 * p][1] = r4[1];
                b[2 * p + 1][0] = r4[2]; b[2 * p + 1][1] = r4[3];
            }
#pragma unroll
            for (int ti = 0; ti < 2; ++ti)
#pragma unroll
                for (int nj = 0; nj < 8; ++nj)
                    mma16816(acc[ti][nj], a[ti], b[nj]);
        }
        __syncthreads();
    }

    const int row_base = bm + wr * 32;
    const int col_base = bn + wc * 64;
#pragma unroll
    for (int ti = 0; ti < 2; ++ti) {
        int r0 = row_base + ti * 16 + (lane >> 2);
#pragma unroll
        for (int nj = 0; nj < 8; ++nj) {
            int col = col_base + nj * 8 + (lane & 3) * 2;
            float b0 = bias[col], b1 = bias[col + 1];
            float v00 = acc[ti][nj][0] + b0, v01 = acc[ti][nj][1] + b1;
            float v10 = acc[ti][nj][2] + b0, v11 = acc[ti][nj][3] + b1;
            if (EPI == 1) {
                v00 = gelu_tanh(v00); v01 = gelu_tanh(v01);
                v10 = gelu_tanh(v10); v11 = gelu_tanh(v11);
            }
            if (SCALEQ && col < CDIM) {
                v00 *= QSCALE; v01 *= QSCALE;
                v10 *= QSCALE; v11 *= QSCALE;
            }
            size_t o0 = (size_t)r0 * N + col;
            size_t o1 = (size_t)(r0 + 8) * N + col;
            if (EPI == 2) {
                v00 += Res[o0]; v01 += Res[o0 + 1];
                v10 += Res[o1]; v11 += Res[o1 + 1];
            }
            if (STOREF) {
                float2 f0; f0.x = v00; f0.y = v01;
                float2 f1; f1.x = v10; f1.y = v11;
                *(float2*)(C + o0) = f0;
                *(float2*)(C + o1) = f1;
            }
            if (STOREH) {
                *(uint32_t*)(Ch + o0) = packh(v00, v01);
                *(uint32_t*)(Ch + o1) = packh(v10, v11);
            }
        }
    }
}

// ---------------- Flash attention, fp16 TC, software-pipelined -------
// Br=128 (8 warps), Bc=64. 4-stage KV ring.
// Per tile: QK(t) -> PV(t-1) -> softmax(t); PV deferred one tile so the
// softmax's wait on QK results is covered by PV MMAs.
#define FAP 72
#define FA_Q_ELEMS (128 * FAP)
#define FA_KV_ELEMS (64 * FAP)
#define FA2_SMEM ((FA_Q_ELEMS + 8 * FA_KV_ELEMS) * 2)

__global__ __launch_bounds__(256, 2) void flash_attn_tc(
    const __half* __restrict__ qkv, __half* __restrict__ outp)
{
    extern __shared__ __half sb[];
    __half* sQ = sb;                       // [128][72]
    __half* sKV = sQ + FA_Q_ELEMS;         // [4][K,V][64][72]

    const int tid = threadIdx.x, lane = tid & 31, w = tid >> 5;
    const int b = blockIdx.z, h = blockIdx.y;
    const int qtb = (gridDim.x - 1) - blockIdx.x;   // heavy tiles first
    const int q0 = qtb * 128;
    const size_t rs = 3 * CDIM;
    const __half* base = qkv + (size_t)b * TSEQ * rs + h * HD;

    auto loadKV = [&](int kt) {
        const int k0 = kt * 64;
        __half* d = sKV + (kt & 3) * 2 * FA_KV_ELEMS;
        const __half* srcs[2] = { base + CDIM, base + 2 * CDIM };
#pragma unroll
        for (int a = 0; a < 2; a++) {
#pragma unroll
            for (int i = 0; i < 2; i++) {
                int id = tid + i * 256;
                int r = id >> 3, c8 = id & 7;
                cp16(smem_u32(d + a * FA_KV_ELEMS + r * FAP + c8 * 8),
                     srcs[a] + (size_t)(k0 + r) * rs + c8 * 8);
            }
        }
    };

#pragma unroll
    for (int i = 0; i < 4; i++) {
        int id = tid + i * 256;
        int r = id >> 3, c8 = id & 7;
        cp16(smem_u32(sQ + r * FAP + c8 * 8), base + (size_t)(q0 + r) * rs + c8 * 8);
    }
    loadKV(0);
    loadKV(1);
    cp_commit();

    float o[8][4];
#pragma unroll
    for (int nt = 0; nt < 8; nt++)
#pragma unroll
        for (int e = 0; e < 4; e++) o[nt][e] = 0.0f;
    float m[2] = {-1e30f, -1e30f}, l[2] = {0.0f, 0.0f};
    uint32_t qf[4][4];
    float s[8][4];
    uint32_t php[8][2];
    bool havePrev = false;
    int prevKt = 0;

    const int NT = 2 * qtb + 2;
    const int rmin = q0 + w * 16;
    const int rmax = rmin + 15;

    auto qk_tile = [&](int kt) {
        __half* Kt = sKV + (kt & 3) * 2 * FA_KV_ELEMS;
#pragma unroll
        for (int nt = 0; nt < 8; nt++)
#pragma unroll
            for (int e = 0; e < 4; e++) s[nt][e] = 0.0f;
#pragma unroll
        for (int ks = 0; ks < 4; ks++) {
            uint32_t kb[8][2];
#pragma unroll
            for (int p = 0; p < 4; p++) {
                uint32_t roff = (uint32_t)((p * 16 + ((lane >> 4) << 3) + (lane & 7)) * FAP
                                           + ks * 16 + (((lane >> 3) & 1) << 3)) * 2;
                uint32_t r4[4];
                ldsm_x4(r4, smem_u32(Kt) + roff);
                kb[2 * p][0] = r4[0]; kb[2 * p][1] = r4[1];
                kb[2 * p + 1][0] = r4[2]; kb[2 * p + 1][1] = r4[3];
            }
#pragma unroll
            for (int t = 0; t < 8; t++) mma16816(s[t], qf[ks], kb[t]);
        }
    };

    auto pv_tile = [&](int kt) {
        __half* Vt = sKV + (kt & 3) * 2 * FA_KV_ELEMS + FA_KV_ELEMS;
#pragma unroll
        for (int ks = 0; ks < 4; ks++) {
            uint32_t pa[4];
            pa[0] = php[2 * ks][0];
            pa[1] = php[2 * ks][1];
            pa[2] = php[2 * ks + 1][0];
            pa[3] = php[2 * ks + 1][1];
            uint32_t vb[8][2];
#pragma unroll
            for (int p = 0; p < 4; p++) {
                uint32_t roff = (uint32_t)((ks * 16 + (lane & 15)) * FAP
                                           + p * 16 + (lane >> 4) * 8) * 2;
                uint32_t r4[4];
                ldsm_x4t(r4, smem_u32(Vt) + roff);
                vb[2 * p][0] = r4[0]; vb[2 * p][1] = r4[1];
                vb[2 * p + 1][0] = r4[2]; vb[2 * p + 1][1] = r4[3];
            }
#pragma unroll
            for (int t = 0; t < 8; t++) mma16816(o[t], pa, vb[t]);
        }
    };

    auto softmax_tile = [&](int k0) {
        if (k0 + 63 > rmin) {
#pragma unroll
            for (int nt = 0; nt < 8; nt++)
#pragma unroll
                for (int e = 0; e < 4; e++) {
                    int col = k0 + nt * 8 + 2 * (lane & 3) + (e & 1);
                    int rr = rmin + (lane >> 2) + (e >> 1) * 8;
                    if (col > rr) s[nt][e] = -1e30f;
                }
        }
#pragma unroll
        for (int half = 0; half < 2; half++) {
            float tm = -1e30f;
#pragma unroll
            for (int nt = 0; nt < 8; nt++)
                tm = fmaxf(tm, fmaxf(s[nt][2 * half], s[nt][2 * half + 1]));
            tm = fmaxf(tm, __shfl_xor_sync(0xffffffffu, tm, 1));
            tm = fmaxf(tm, __shfl_xor_sync(0xffffffffu, tm, 2));
            float mn = fmaxf(m[half], tm);
            float alpha = fast_ex2(m[half] - mn);
            m[half] = mn;
            float ps = 0.0f;
#pragma unroll
            for (int nt = 0; nt < 8; nt++) {
                float e0 = fast_ex2(s[nt][2 * half] - mn);
                float e1 = fast_ex2(s[nt][2 * half + 1] - mn);
                ps += e0 + e1;
                php[nt][half] = packh(e0, e1);
            }
            l[half] = l[half] * alpha + ps;
#pragma unroll
            for (int nt = 0; nt < 8; nt++) {
                o[nt][2 * half]     *= alpha;
                o[nt][2 * half + 1] *= alpha;
            }
        }
    };

    for (int kt0 = 0; kt0 < NT; kt0 += 2) {
        cp_wait<0>();
        __syncthreads();
        if (kt0 == 0) {
#pragma unroll
            for (int ks = 0; ks < 4; ks++) {
                uint32_t off = (uint32_t)((w * 16 + (lane & 15)) * FAP
                                          + ks * 16 + (lane >> 4) * 8) * 2;
                ldsm_x4(qf[ks], smem_u32(sQ) + off);
            }
        }

        // tile t0 = kt0 (always valid)
        qk_tile(kt0);
        if (havePrev) pv_tile(prevKt);
        __syncthreads();   // PV(prev) ldsm done before ring stage is refilled
        if (kt0 + 2 < NT) {
            loadKV(kt0 + 2);
            loadKV(kt0 + 3);
            cp_commit();
        }
        softmax_tile(kt0 * 64);
        prevKt = kt0;
        havePrev = true;

        // tile t1 = kt0 + 1
        const int kt = kt0 + 1;
        if (kt * 64 <= rmax) {
            qk_tile(kt);
            pv_tile(kt0);          // consume php(t0), covers softmax(t1)'s wait
            softmax_tile(kt * 64);
            prevKt = kt;
            havePrev = true;
        } else {
            pv_tile(kt0);
            havePrev = false;
        }
    }
    if (havePrev) pv_tile(prevKt);

    float linv[2];
#pragma unroll
    for (int half = 0; half < 2; half++) {
        float lv = l[half];
        lv += __shfl_xor_sync(0xffffffffu, lv, 1);
        lv += __shfl_xor_sync(0xffffffffu, lv, 2);
        linv[half] = 1.0f / lv;
    }
#pragma unroll
    for (int nt = 0; nt < 8; nt++) {
#pragma unroll
        for (int half = 0; half < 2; half++) {
            int rowg = q0 + w * 16 + (lane >> 2) + half * 8;
            int colg = h * HD + nt * 8 + 2 * (lane & 3);
            float f0 = o[nt][2 * half]     * linv[half];
            float f1 = o[nt][2 * half + 1] * linv[half];
            size_t off = (size_t)(b * TSEQ + rowg) * CDIM + colg;
            *(uint32_t*)(outp + off) = packh(f0, f1);
        }
    }
}

// ---------------- launch ----------------
extern "C" void kernel_launch(void* const* d_in, const int* in_sizes, int n_in,
                              void* d_out, int out_size)
{
    const float* x       = (const float*)d_in[0];
    const float* ln1_w   = (const float*)d_in[1];
    const float* ln1_b   = (const float*)d_in[2];
    const float* attn_w  = (const float*)d_in[3];
    const float* attn_b  = (const float*)d_in[4];
    const float* proj_w  = (const float*)d_in[5];
    const float* proj_b  = (const float*)d_in[6];
    const float* ln2_w   = (const float*)d_in[7];
    const float* ln2_b   = (const float*)d_in[8];
    const float* fc_w    = (const float*)d_in[9];
    const float* fc_b    = (const float*)d_in[10];
    const float* mproj_w = (const float*)d_in[11];
    const float* mproj_b = (const float*)d_in[12];
    float* out = (float*)d_out;

    __half *ln, *qkv, *att, *fc, *wv;
    float *x1;
    cudaGetSymbolAddress((void**)&ln,  g_ln);
    cudaGetSymbolAddress((void**)&qkv, g_qkv);
    cudaGetSymbolAddress((void**)&att, g_att);
    cudaGetSymbolAddress((void**)&x1,  g_x1);
    cudaGetSymbolAddress((void**)&fc,  g_fc);
    cudaGetSymbolAddress((void**)&wv,  g_w);

    __half *wqkv = wv;
    __half *wproj = wv + W_QKV_N;
    __half *wfc = wproj + W_PROJ_N;
    __half *wmp = wfc + W_FC_N;

    cudaFuncSetAttribute(flash_attn_tc,
                         cudaFuncAttributeMaxDynamicSharedMemorySize, FA2_SMEM);
    cudaFuncSetAttribute((const void*)hgemm<0, false, true, true>,
                         cudaFuncAttributeMaxDynamicSharedMemorySize, GEMM_SMEM_BYTES);
    cudaFuncSetAttribute((const void*)hgemm<2, true, false, false>,
                         cudaFuncAttributeMaxDynamicSharedMemorySize, GEMM_SMEM_BYTES);
    cudaFuncSetAttribute((const void*)hgemm<1, false, true, false>,
                         cudaFuncAttributeMaxDynamicSharedMemorySize, GEMM_SMEM_BYTES);

    // 0) convert all weights to fp16 (single launch)
    cvt_all_kernel<<<(N4_TOTAL + 255) / 256, 256>>>(
        (const float4*)attn_w, (const float4*)proj_w,
        (const float4*)fc_w, (const float4*)mproj_w, (uint32_t*)wv);

    // 1) ln1 -> fp16
    ln_kernel<<<MROWS, 256>>>(x, ln1_w, ln1_b, ln);
    // 2) qkv = ln1 @ W_attn + b (q cols pre-scaled by QSCALE) -> fp16
    hgemm<0, false, true, true><<<dim3(2304 / 128, MROWS / 128), 256, GEMM_SMEM_BYTES>>>(
        MROWS, 2304, CDIM, ln, wqkv, attn_b, nullptr, nullptr, qkv);
    // 3) attention -> fp16
    flash_attn_tc<<<dim3(TSEQ / 128, NHEAD, NBATCH), 256, FA2_SMEM>>>(qkv, att);
    // 4) x1 = x + att @ W_proj + b   (fp32)
    hgemm<2, true, false, false><<<dim3(CDIM / 128, MROWS / 128), 256, GEMM_SMEM_BYTES>>>(
        MROWS, CDIM, CDIM, att, wproj, proj_b, x, x1, nullptr);
    // 5) ln2 -> fp16
    ln_kernel<<<MROWS, 256>>>(x1, ln2_w, ln2_b, ln);
    // 6) fc = gelu(ln2 @ W_fc + b)   [8192, 3072] -> fp16
    hgemm<1, false, true, false><<<dim3(3072 / 128, MROWS / 128), 256, GEMM_SMEM_BYTES>>>(
        MROWS, 3072, CDIM, ln, wfc, fc_b, nullptr, nullptr, fc);
    // 7) out = x1 + fc @ W_mproj + b   (fp32)
    hgemm<2, true, false, false><<<dim3(CDIM / 128, MROWS / 128), 256, GEMM_SMEM_BYTES>>>(
        MROWS, CDIM, 4 * CDIM, fc, wmp, mproj_b, x1, out, nullptr);
}

// round 15
// speedup vs baseline: 1.0079x; 1.0079x over previous
#include <cuda_runtime.h>
#include <cuda_fp16.h>
#include <math.h>
#include <stdint.h>

#define MROWS 8192           // B*T = 4*2048
#define CDIM  768
#define TSEQ  2048
#define NBATCH 4
#define NHEAD 12
#define HD    64

// ---------------- scratch (no allocations allowed) ----------------
__device__ __half g_ln [(size_t)MROWS * CDIM];
__device__ __half g_qkv[(size_t)MROWS * 3 * CDIM];
__device__ __half g_att[(size_t)MROWS * CDIM];
__device__ float  g_x1 [(size_t)MROWS * CDIM];
__device__ __half g_fc [(size_t)MROWS * 4 * CDIM];

#define W_QKV_N (768*2304)
#define W_PROJ_N (768*768)
#define W_FC_N (768*3072)
#define W_MP_N (3072*768)
__device__ __half g_w[W_QKV_N + W_PROJ_N + W_FC_N + W_MP_N];

// softmax scale folded into q at qkv epilogue: 0.125 * log2(e)
#define QSCALE 0.18033688011112042f

// ---------------- helpers ----------------
__device__ __forceinline__ float warp_sum(float v) {
#pragma unroll
    for (int m = 16; m; m >>= 1) v += __shfl_xor_sync(0xffffffffu, v, m);
    return v;
}

__device__ __forceinline__ float fast_ex2(float x) {
    float y;
    asm("ex2.approx.ftz.f32 %0, %1;" : "=f"(y) : "f"(x));
    return y;
}
__device__ __forceinline__ float fast_rcp(float x) {
    float y;
    asm("rcp.approx.ftz.f32 %0, %1;" : "=f"(y) : "f"(x));
    return y;
}

__device__ __forceinline__ float gelu_tanh(float x) {
    const float c = 0.7978845608028654f;  // sqrt(2/pi)
    float u = c * (x + 0.044715f * x * x * x);
    float t = fast_ex2(2.885390081777927f * u);   // exp(2u)
    float th = 1.0f - 2.0f * fast_rcp(t + 1.0f);
    return 0.5f * x * (1.0f + th);
}

__device__ __forceinline__ uint32_t smem_u32(const void* p) {
    return (uint32_t)__cvta_generic_to_shared(p);
}

__device__ __forceinline__ void cp16(uint32_t dst, const void* src) {
    asm volatile("cp.async.cg.shared.global [%0], [%1], 16;\n" :: "r"(dst), "l"(src));
}
__device__ __forceinline__ void cp_commit() { asm volatile("cp.async.commit_group;\n"); }
template<int N> __device__ __forceinline__ void cp_wait() {
    asm volatile("cp.async.wait_group %0;\n" :: "n"(N));
}

__device__ __forceinline__ void ldsm_x4(uint32_t (&r)[4], uint32_t addr) {
    asm volatile("ldmatrix.sync.aligned.m8n8.x4.shared.b16 {%0,%1,%2,%3}, [%4];"
        : "=r"(r[0]), "=r"(r[1]), "=r"(r[2]), "=r"(r[3]) : "r"(addr));
}
__device__ __forceinline__ void ldsm_x4t(uint32_t (&r)[4], uint32_t addr) {
    asm volatile("ldmatrix.sync.aligned.m8n8.x4.trans.shared.b16 {%0,%1,%2,%3}, [%4];"
        : "=r"(r[0]), "=r"(r[1]), "=r"(r[2]), "=r"(r[3]) : "r"(addr));
}
__device__ __forceinline__ void mma16816(float (&d)[4], const uint32_t (&a)[4],
                                         const uint32_t (&b)[2]) {
    asm volatile(
        "mma.sync.aligned.m16n8k16.row.col.f32.f16.f16.f32 "
        "{%0,%1,%2,%3},{%4,%5,%6,%7},{%8,%9},{%0,%1,%2,%3};"
        : "+f"(d[0]), "+f"(d[1]), "+f"(d[2]), "+f"(d[3])
        : "r"(a[0]), "r"(a[1]), "r"(a[2]), "r"(a[3]), "r"(b[0]), "r"(b[1]));
}

__device__ __forceinline__ uint32_t packh(float a, float b) {
    __half2 h = __floats2half2_rn(a, b);
    return *(uint32_t*)&h;
}

// ---------------- fused weight convert f32 -> fp16 (one launch) ------
#define N4_QKV (W_QKV_N / 4)
#define N4_PROJ (W_PROJ_N / 4)
#define N4_FC (W_FC_N / 4)
#define N4_MP (W_MP_N / 4)
#define N4_TOTAL (N4_QKV + N4_PROJ + N4_FC + N4_MP)

__global__ __launch_bounds__(256) void cvt_all_kernel(
    const float4* __restrict__ w0, const float4* __restrict__ w1,
    const float4* __restrict__ w2, const float4* __restrict__ w3,
    uint32_t* __restrict__ h)
{
    int i = blockIdx.x * 256 + threadIdx.x;
    if (i >= N4_TOTAL) return;
    const float4* src;
    int j = i;
    if (j < N4_QKV) { src = w0; }
    else if ((j -= N4_QKV) < N4_PROJ) { src = w1; }
    else if ((j -= N4_PROJ) < N4_FC) { src = w2; }
    else { j -= N4_FC; src = w3; }
    float4 v = src[j];
    h[2 * i]     = packh(v.x, v.y);
    h[2 * i + 1] = packh(v.z, v.w);
}

// ---------------- LayerNorm (row = 768, ddof=1) -> fp16 --------
__global__ __launch_bounds__(256) void ln_kernel(
    const float* __restrict__ x, const float* __restrict__ w,
    const float* __restrict__ b, __half* __restrict__ y)
{
    const int row = blockIdx.x;
    const float* xr = x + (size_t)row * CDIM;
    const int t = threadIdx.x;

    float v0 = xr[t], v1 = xr[t + 256], v2 = xr[t + 512];
    float s  = v0 + v1 + v2;
    float s2 = v0 * v0 + v1 * v1 + v2 * v2;

    __shared__ float sh[2][8];
    s = warp_sum(s); s2 = warp_sum(s2);
    int wid = t >> 5, lane = t & 31;
    if (lane == 0) { sh[0][wid] = s; sh[1][wid] = s2; }
    __syncthreads();
    if (wid == 0) {
        float a = (lane < 8) ? sh[0][lane] : 0.0f;
        float c = (lane < 8) ? sh[1][lane] : 0.0f;
        a = warp_sum(a); c = warp_sum(c);
        if (lane == 0) { sh[0][0] = a; sh[1][0] = c; }
    }
    __syncthreads();
    s = sh[0][0]; s2 = sh[1][0];

    float mean = s * (1.0f / (float)CDIM);
    float var  = (s2 - (float)CDIM * mean * mean) * (1.0f / (float)(CDIM - 1));
    float rstd = rsqrtf(var + 1e-5f);

    size_t base = (size_t)row * CDIM;
#pragma unroll
    for (int j = 0; j < 3; j++) {
        int c = t + j * 256;
        float v = (j == 0 ? v0 : (j == 1 ? v1 : v2));
        y[base + c] = __float2half_rn((v - mean) * rstd * w[c] + b[c]);
    }
}

// ---------------- fp16 tensor-core GEMM, 128x128x32 ----------------
// EPI: 0=+bias, 1=gelu(+bias), 2=+bias+residual.
// SCALEQ: multiply output cols < CDIM by QSCALE (qkv call only).
#define GEMM_SMEM_ELEMS ((2*128*40) + (2*32*136))
#define GEMM_SMEM_BYTES (GEMM_SMEM_ELEMS * 2)

template<int EPI, bool STOREF, bool STOREH, bool SCALEQ>
__global__ __launch_bounds__(256, 2) void hgemm(
    int M, int N, int K,
    const __half* __restrict__ A, const __half* __restrict__ B,
    const float* __restrict__ bias, const float* __restrict__ Res,
    float* __restrict__ C, __half* __restrict__ Ch)
{
    extern __shared__ __half sm[];
    __half* sA = sm;                    // [2][128][40]
    __half* sB = sA + 2 * 128 * 40;     // [2][32][136]
    const uint32_t uA = smem_u32(sA), uB = smem_u32(sB);

    const int tid  = threadIdx.x;
    const int warp = tid >> 5, lane = tid & 31;
    const int wr = warp >> 1, wc = warp & 1;
    const int bm = blockIdx.y * 128, bn = blockIdx.x * 128;

    float acc[2][8][4];
#pragma unroll
    for (int i = 0; i < 2; i++)
#pragma unroll
        for (int j = 0; j < 8; j++)
#pragma unroll
            for (int k = 0; k < 4; k++) acc[i][j][k] = 0.0f;

    auto load_tile = [&](int kt, int buf) {
#pragma unroll
        for (int i = 0; i < 2; i++) {
            int id = tid + i * 256;
            int r = id >> 2, c = id & 3;
            uint32_t off = (uint32_t)((buf * 128 + r) * 40 + c * 8) * 2;
            cp16(uA + off, A + (size_t)(bm + r) * K + kt * 32 + c * 8);
        }
#pragma unroll
        for (int i = 0; i < 2; i++) {
            int id = tid + i * 256;
            int r = id >> 4, c = id & 15;
            uint32_t off = (uint32_t)((buf * 32 + r) * 136 + c * 8) * 2;
            cp16(uB + off, B + (size_t)(kt * 32 + r) * N + bn + c * 8);
        }
    };

    const int KT = K >> 5;
    load_tile(0, 0);
    cp_commit();

    for (int kt = 0; kt < KT; ++kt) {
        const int buf = kt & 1;
        if (kt + 1 < KT) {
            load_tile(kt + 1, buf ^ 1);
            cp_commit();
            cp_wait<1>();
        } else {
            cp_wait<0>();
        }
        __syncthreads();

#pragma unroll
        for (int ks = 0; ks < 2; ++ks) {
            uint32_t a[2][4], b[8][2];
#pragma unroll
            for (int ti = 0; ti < 2; ++ti) {
                int r = wr * 32 + ti * 16 + (lane & 15);
                int col = ks * 16 + (lane >> 4) * 8;
                ldsm_x4(a[ti], uA + (uint32_t)((buf * 128 + r) * 40 + col) * 2);
            }
#pragma unroll
            for (int p = 0; p < 4; ++p) {
                int kr = ks * 16 + (lane & 15);
                int col = wc * 64 + p * 16 + (lane >> 4) * 8;
                uint32_t r4[4];
                ldsm_x4t(r4, uB + (uint32_t)((buf * 32 + kr) * 136 + col) * 2);
                b[2 * p][0] = r4[0]; b[2 * p][1] = r4[1];
                b[2 * p + 1][0] = r4[2]; b[2 * p + 1][1] = r4[3];
            }
#pragma unroll
            for (int ti = 0; ti < 2; ++ti)
#pragma unroll
                for (int nj = 0; nj < 8; ++nj)
                    mma16816(acc[ti][nj], a[ti], b[nj]);
        }
        __syncthreads();
    }

    const int row_base = bm + wr * 32;
    const int col_base = bn + wc * 64;
#pragma unroll
    for (int ti = 0; ti < 2; ++ti) {
        int r0 = row_base + ti * 16 + (lane >> 2);
#pragma unroll
        for (int nj = 0; nj < 8; ++nj) {
            int col = col_base + nj * 8 + (lane & 3) * 2;
            float b0 = bias[col], b1 = bias[col + 1];
            float v00 = acc[ti][nj][0] + b0, v01 = acc[ti][nj][1] + b1;
            float v10 = acc[ti][nj][2] + b0, v11 = acc[ti][nj][3] + b1;
            if (EPI == 1) {
                v00 = gelu_tanh(v00); v01 = gelu_tanh(v01);
                v10 = gelu_tanh(v10); v11 = gelu_tanh(v11);
            }
            if (SCALEQ && col < CDIM) {
                v00 *= QSCALE; v01 *= QSCALE;
                v10 *= QSCALE; v11 *= QSCALE;
            }
            size_t o0 = (size_t)r0 * N + col;
            size_t o1 = (size_t)(r0 + 8) * N + col;
            if (EPI == 2) {
                v00 += Res[o0]; v01 += Res[o0 + 1];
                v10 += Res[o1]; v11 += Res[o1 + 1];
            }
            if (STOREF) {
                float2 f0; f0.x = v00; f0.y = v01;
                float2 f1; f1.x = v10; f1.y = v11;
                *(float2*)(C + o0) = f0;
                *(float2*)(C + o1) = f1;
            }
            if (STOREH) {
                *(uint32_t*)(Ch + o0) = packh(v00, v01);
                *(uint32_t*)(Ch + o1) = packh(v10, v11);
            }
        }
    }
}

// ---------------- Flash attention, fp16 tensor cores (R12 layout) ----
// Br=128 (8 warps), Bc=64. 4-stage KV ring, 1 barrier per 2 tiles.
// Q pre-scaled by QSCALE. O-rescale skipped (warp-uniform branch) when
// no row in the warp updated its running max (alpha == 1 exactly).
#define FAP 72
#define FA_Q_ELEMS (128 * FAP)
#define FA_KV_ELEMS (64 * FAP)
#define FA2_SMEM ((FA_Q_ELEMS + 8 * FA_KV_ELEMS) * 2)

__global__ __launch_bounds__(256, 2) void flash_attn_tc(
    const __half* __restrict__ qkv, __half* __restrict__ outp)
{
    extern __shared__ __half sb[];
    __half* sQ = sb;                       // [128][72]
    __half* sKV = sQ + FA_Q_ELEMS;         // [4][K,V][64][72]

    const int tid = threadIdx.x, lane = tid & 31, w = tid >> 5;
    const int b = blockIdx.z, h = blockIdx.y;
    const int qtb = (gridDim.x - 1) - blockIdx.x;   // heavy tiles first
    const int q0 = qtb * 128;
    const size_t rs = 3 * CDIM;
    const __half* base = qkv + (size_t)b * TSEQ * rs + h * HD;

    auto loadKV = [&](int kt) {
        const int k0 = kt * 64;
        __half* d = sKV + (kt & 3) * 2 * FA_KV_ELEMS;
        const __half* srcs[2] = { base + CDIM, base + 2 * CDIM };
#pragma unroll
        for (int a = 0; a < 2; a++) {
#pragma unroll
            for (int i = 0; i < 2; i++) {
                int id = tid + i * 256;
                int r = id >> 3, c8 = id & 7;
                cp16(smem_u32(d + a * FA_KV_ELEMS + r * FAP + c8 * 8),
                     srcs[a] + (size_t)(k0 + r) * rs + c8 * 8);
            }
        }
    };

#pragma unroll
    for (int i = 0; i < 4; i++) {
        int id = tid + i * 256;
        int r = id >> 3, c8 = id & 7;
        cp16(smem_u32(sQ + r * FAP + c8 * 8), base + (size_t)(q0 + r) * rs + c8 * 8);
    }
    loadKV(0);
    loadKV(1);
    cp_commit();

    float o[8][4];
#pragma unroll
    for (int nt = 0; nt < 8; nt++)
#pragma unroll
        for (int e = 0; e < 4; e++) o[nt][e] = 0.0f;
    float m[2] = {-1e30f, -1e30f}, l[2] = {0.0f, 0.0f};
    uint32_t qf[4][4];

    const int NT = 2 * qtb + 2;
    const int rmin = q0 + w * 16;
    const int rmax = rmin + 15;

    for (int kt0 = 0; kt0 < NT; kt0 += 2) {
        cp_wait<0>();
        __syncthreads();
        if (kt0 + 2 < NT) {
            loadKV(kt0 + 2);
            loadKV(kt0 + 3);
            cp_commit();
        }
        if (kt0 == 0) {
#pragma unroll
            for (int ks = 0; ks < 4; ks++) {
                uint32_t off = (uint32_t)((w * 16 + (lane & 15)) * FAP
                                          + ks * 16 + (lane >> 4) * 8) * 2;
                ldsm_x4(qf[ks], smem_u32(sQ) + off);
            }
        }

#pragma unroll
        for (int sub = 0; sub < 2; sub++) {
            const int kt = kt0 + sub;
            const int k0 = kt * 64;
            if (k0 > rmax) continue;
            __half* Kt = sKV + (kt & 3) * 2 * FA_KV_ELEMS;
            __half* Vt = Kt + FA_KV_ELEMS;

            float s[8][4];
#pragma unroll
            for (int nt = 0; nt < 8; nt++)
#pragma unroll
                for (int e = 0; e < 4; e++) s[nt][e] = 0.0f;

            // S = Q K^T  (log2 domain via pre-scaled Q)
#pragma unroll
            for (int ks = 0; ks < 4; ks++) {
                uint32_t kb[8][2];
#pragma unroll
                for (int p = 0; p < 4; p++) {
                    uint32_t roff = (uint32_t)((p * 16 + ((lane >> 4) << 3) + (lane & 7)) * FAP
                                               + ks * 16 + (((lane >> 3) & 1) << 3)) * 2;
                    uint32_t r4[4];
                    ldsm_x4(r4, smem_u32(Kt) + roff);
                    kb[2 * p][0] = r4[0]; kb[2 * p][1] = r4[1];
                    kb[2 * p + 1][0] = r4[2]; kb[2 * p + 1][1] = r4[3];
                }
#pragma unroll
                for (int t = 0; t < 8; t++) mma16816(s[t], qf[ks], kb[t]);
            }

            if (k0 + 63 > rmin) {
#pragma unroll
                for (int nt = 0; nt < 8; nt++)
#pragma unroll
                    for (int e = 0; e < 4; e++) {
                        int col = k0 + nt * 8 + 2 * (lane & 3) + (e & 1);
                        int rr = rmin + (lane >> 2) + (e >> 1) * 8;
                        if (col > rr) s[nt][e] = -1e30f;
                    }
            }

            // online softmax; skip O-rescale when warp saw no max update
            bool upd = false;
            float alpha_[2];
#pragma unroll
            for (int half = 0; half < 2; half++) {
                float tm = -1e30f;
#pragma unroll
                for (int nt = 0; nt < 8; nt++)
                    tm = fmaxf(tm, fmaxf(s[nt][2 * half], s[nt][2 * half + 1]));
                tm = fmaxf(tm, __shfl_xor_sync(0xffffffffu, tm, 1));
                tm = fmaxf(tm, __shfl_xor_sync(0xffffffffu, tm, 2));
                float mold = m[half];
                float mn = fmaxf(mold, tm);
                upd |= (tm > mold);
                alpha_[half] = fast_ex2(mold - mn);
                m[half] = mn;
                float ps = 0.0f;
#pragma unroll
                for (int nt = 0; nt < 8; nt++) {
                    s[nt][2 * half]     = fast_ex2(s[nt][2 * half] - mn);
                    s[nt][2 * half + 1] = fast_ex2(s[nt][2 * half + 1] - mn);
                    ps += s[nt][2 * half] + s[nt][2 * half + 1];
                }
                l[half] = l[half] * alpha_[half] + ps;
            }
            if (__any_sync(0xffffffffu, upd)) {
#pragma unroll
                for (int half = 0; half < 2; half++)
#pragma unroll
                    for (int nt = 0; nt < 8; nt++) {
                        o[nt][2 * half]     *= alpha_[half];
                        o[nt][2 * half + 1] *= alpha_[half];
                    }
            }

            // O += P V
#pragma unroll
            for (int ks = 0; ks < 4; ks++) {
                uint32_t pa[4];
                pa[0] = packh(s[2 * ks][0],     s[2 * ks][1]);
                pa[1] = packh(s[2 * ks][2],     s[2 * ks][3]);
                pa[2] = packh(s[2 * ks + 1][0], s[2 * ks + 1][1]);
                pa[3] = packh(s[2 * ks + 1][2], s[2 * ks + 1][3]);
                uint32_t vb[8][2];
#pragma unroll
                for (int p = 0; p < 4; p++) {
                    uint32_t roff = (uint32_t)((ks * 16 + (lane & 15)) * FAP
                                               + p * 16 + (lane >> 4) * 8) * 2;
                    uint32_t r4[4];
                    ldsm_x4t(r4, smem_u32(Vt) + roff);
                    vb[2 * p][0] = r4[0]; vb[2 * p][1] = r4[1];
                    vb[2 * p + 1][0] = r4[2]; vb[2 * p + 1][1] = r4[3];
                }
#pragma unroll
                for (int t = 0; t < 8; t++) mma16816(o[t], pa, vb[t]);
            }
        }
    }

    float linv[2];
#pragma unroll
    for (int half = 0; half < 2; half++) {
        float lv = l[half];
        lv += __shfl_xor_sync(0xffffffffu, lv, 1);
        lv += __shfl_xor_sync(0xffffffffu, lv, 2);
        linv[half] = 1.0f / lv;
    }
#pragma unroll
    for (int nt = 0; nt < 8; nt++) {
#pragma unroll
        for (int half = 0; half < 2; half++) {
            int rowg = q0 + w * 16 + (lane >> 2) + half * 8;
            int colg = h * HD + nt * 8 + 2 * (lane & 3);
            float f0 = o[nt][2 * half]     * linv[half];
            float f1 = o[nt][2 * half + 1] * linv[half];
            size_t off = (size_t)(b * TSEQ + rowg) * CDIM + colg;
            *(uint32_t*)(outp + off) = packh(f0, f1);
        }
    }
}

// ---------------- launch ----------------
extern "C" void kernel_launch(void* const* d_in, const int* in_sizes, int n_in,
                              void* d_out, int out_size)
{
    const float* x       = (const float*)d_in[0];
    const float* ln1_w   = (const float*)d_in[1];
    const float* ln1_b   = (const float*)d_in[2];
    const float* attn_w  = (const float*)d_in[3];
    const float* attn_b  = (const float*)d_in[4];
    const float* proj_w  = (const float*)d_in[5];
    const float* proj_b  = (const float*)d_in[6];
    const float* ln2_w   = (const float*)d_in[7];
    const float* ln2_b   = (const float*)d_in[8];
    const float* fc_w    = (const float*)d_in[9];
    const float* fc_b    = (const float*)d_in[10];
    const float* mproj_w = (const float*)d_in[11];
    const float* mproj_b = (const float*)d_in[12];
    float* out = (float*)d_out;

    __half *ln, *qkv, *att, *fc, *wv;
    float *x1;
    cudaGetSymbolAddress((void**)&ln,  g_ln);
    cudaGetSymbolAddress((void**)&qkv, g_qkv);
    cudaGetSymbolAddress((void**)&att, g_att);
    cudaGetSymbolAddress((void**)&x1,  g_x1);
    cudaGetSymbolAddress((void**)&fc,  g_fc);
    cudaGetSymbolAddress((void**)&wv,  g_w);

    __half *wqkv = wv;
    __half *wproj = wv + W_QKV_N;
    __half *wfc = wproj + W_PROJ_N;
    __half *wmp = wfc + W_FC_N;

    cudaFuncSetAttribute(flash_attn_tc,
                         cudaFuncAttributeMaxDynamicSharedMemorySize, FA2_SMEM);
    cudaFuncSetAttribute((const void*)hgemm<0, false, true, true>,
                         cudaFuncAttributeMaxDynamicSharedMemorySize, GEMM_SMEM_BYTES);
    cudaFuncSetAttribute((const void*)hgemm<2, true, false, false>,
                         cudaFuncAttributeMaxDynamicSharedMemorySize, GEMM_SMEM_BYTES);
    cudaFuncSetAttribute((const void*)hgemm<1, false, true, false>,
                         cudaFuncAttributeMaxDynamicSharedMemorySize, GEMM_SMEM_BYTES);

    // 0) convert all weights to fp16 (single launch)
    cvt_all_kernel<<<(N4_TOTAL + 255) / 256, 256>>>(
        (const float4*)attn_w, (const float4*)proj_w,
        (const float4*)fc_w, (const float4*)mproj_w, (uint32_t*)wv);

    // 1) ln1 -> fp16
    ln_kernel<<<MROWS, 256>>>(x, ln1_w, ln1_b, ln);
    // 2) qkv = ln1 @ W_attn + b (q cols pre-scaled by QSCALE) -> fp16
    hgemm<0, false, true, true><<<dim3(2304 / 128, MROWS / 128), 256, GEMM_SMEM_BYTES>>>(
        MROWS, 2304, CDIM, ln, wqkv, attn_b, nullptr, nullptr, qkv);
    // 3) attention -> fp16
    flash_attn_tc<<<dim3(TSEQ / 128, NHEAD, NBATCH), 256, FA2_SMEM>>>(qkv, att);
    // 4) x1 = x + att @ W_proj + b   (fp32)
    hgemm<2, true, false, false><<<dim3(CDIM / 128, MROWS / 128), 256, GEMM_SMEM_BYTES>>>(
        MROWS, CDIM, CDIM, att, wproj, proj_b, x, x1, nullptr);
    // 5) ln2 -> fp16
    ln_kernel<<<MROWS, 256>>>(x1, ln2_w, ln2_b, ln);
    // 6) fc = gelu(ln2 @ W_fc + b)   [8192, 3072] -> fp16
    hgemm<1, false, true, false><<<dim3(3072 / 128, MROWS / 128), 256, GEMM_SMEM_BYTES>>>(
        MROWS, 3072, CDIM, ln, wfc, fc_b, nullptr, nullptr, fc);
    // 7) out = x1 + fc @ W_mproj + b   (fp32)
    hgemm<2, true, false, false><<<dim3(CDIM / 128, MROWS / 128), 256, GEMM_SMEM_BYTES>>>(
        MROWS, CDIM, 4 * CDIM, fc, wmp, mproj_b, x1, out, nullptr);
}

// round 16
// speedup vs baseline: 1.0157x; 1.0078x over previous
#include <cuda_runtime.h>
#include <cuda_fp16.h>
#include <math.h>
#include <stdint.h>

#define MROWS 8192           // B*T = 4*2048
#define CDIM  768
#define TSEQ  2048
#define NBATCH 4
#define NHEAD 12
#define HD    64

// ---------------- scratch (no allocations allowed) ----------------
__device__ __half g_ln [(size_t)MROWS * CDIM];
__device__ __half g_qkv[(size_t)MROWS * 3 * CDIM];
__device__ __half g_att[(size_t)MROWS * CDIM];
__device__ float  g_x1 [(size_t)MROWS * CDIM];
__device__ __half g_fc [(size_t)MROWS * 4 * CDIM];

#define W_QKV_N (768*2304)
#define W_PROJ_N (768*768)
#define W_FC_N (768*3072)
#define W_MP_N (3072*768)
__device__ __half g_w[W_QKV_N + W_PROJ_N + W_FC_N + W_MP_N];

// softmax scale folded into q at qkv epilogue: 0.125 * log2(e)
#define QSCALE 0.18033688011112042f

// ---------------- helpers ----------------
__device__ __forceinline__ float warp_sum(float v) {
#pragma unroll
    for (int m = 16; m; m >>= 1) v += __shfl_xor_sync(0xffffffffu, v, m);
    return v;
}

__device__ __forceinline__ float fast_ex2(float x) {
    float y;
    asm("ex2.approx.ftz.f32 %0, %1;" : "=f"(y) : "f"(x));
    return y;
}
__device__ __forceinline__ float fast_rcp(float x) {
    float y;
    asm("rcp.approx.ftz.f32 %0, %1;" : "=f"(y) : "f"(x));
    return y;
}

__device__ __forceinline__ float gelu_tanh(float x) {
    const float c = 0.7978845608028654f;  // sqrt(2/pi)
    float u = c * (x + 0.044715f * x * x * x);
    float t = fast_ex2(2.885390081777927f * u);   // exp(2u)
    float th = 1.0f - 2.0f * fast_rcp(t + 1.0f);
    return 0.5f * x * (1.0f + th);
}

__device__ __forceinline__ uint32_t smem_u32(const void* p) {
    return (uint32_t)__cvta_generic_to_shared(p);
}

__device__ __forceinline__ void cp16(uint32_t dst, const void* src) {
    asm volatile("cp.async.cg.shared.global [%0], [%1], 16;\n" :: "r"(dst), "l"(src));
}
__device__ __forceinline__ void cp_commit() { asm volatile("cp.async.commit_group;\n"); }
template<int N> __device__ __forceinline__ void cp_wait() {
    asm volatile("cp.async.wait_group %0;\n" :: "n"(N));
}

__device__ __forceinline__ void ldsm_x4(uint32_t (&r)[4], uint32_t addr) {
    asm volatile("ldmatrix.sync.aligned.m8n8.x4.shared.b16 {%0,%1,%2,%3}, [%4];"
        : "=r"(r[0]), "=r"(r[1]), "=r"(r[2]), "=r"(r[3]) : "r"(addr));
}
__device__ __forceinline__ void ldsm_x4t(uint32_t (&r)[4], uint32_t addr) {
    asm volatile("ldmatrix.sync.aligned.m8n8.x4.trans.shared.b16 {%0,%1,%2,%3}, [%4];"
        : "=r"(r[0]), "=r"(r[1]), "=r"(r[2]), "=r"(r[3]) : "r"(addr));
}
__device__ __forceinline__ void mma16816(float (&d)[4], const uint32_t (&a)[4],
                                         const uint32_t (&b)[2]) {
    asm volatile(
        "mma.sync.aligned.m16n8k16.row.col.f32.f16.f16.f32 "
        "{%0,%1,%2,%3},{%4,%5,%6,%7},{%8,%9},{%0,%1,%2,%3};"
        : "+f"(d[0]), "+f"(d[1]), "+f"(d[2]), "+f"(d[3])
        : "r"(a[0]), "r"(a[1]), "r"(a[2]), "r"(a[3]), "r"(b[0]), "r"(b[1]));
}

__device__ __forceinline__ uint32_t packh(float a, float b) {
    __half2 h = __floats2half2_rn(a, b);
    return *(uint32_t*)&h;
}

// ---------------- weight segment table -------------------------------
#define N4_QKV (W_QKV_N / 4)
#define N4_PROJ (W_PROJ_N / 4)
#define N4_FC (W_FC_N / 4)
#define N4_MP (W_MP_N / 4)
#define N4_TOTAL (N4_QKV + N4_PROJ + N4_FC + N4_MP)

// ---------------- LayerNorm (row = 768, ddof=1) -> fp16 --------------
// CVT=true also converts one float4 of weights per thread (fused
// weight-conversion: 8192 blocks x 256 threads >= N4_TOTAL float4s).
template<bool CVT>
__global__ __launch_bounds__(256) void ln_kernel(
    const float* __restrict__ x, const float* __restrict__ w,
    const float* __restrict__ b, __half* __restrict__ y,
    const float4* __restrict__ w0, const float4* __restrict__ w1,
    const float4* __restrict__ w2, const float4* __restrict__ w3,
    uint32_t* __restrict__ hw)
{
    const int row = blockIdx.x;
    const float* xr = x + (size_t)row * CDIM;
    const int t = threadIdx.x;

    float v0 = xr[t], v1 = xr[t + 256], v2 = xr[t + 512];
    float s  = v0 + v1 + v2;
    float s2 = v0 * v0 + v1 * v1 + v2 * v2;

    __shared__ float sh[2][8];
    s = warp_sum(s); s2 = warp_sum(s2);
    int wid = t >> 5, lane = t & 31;
    if (lane == 0) { sh[0][wid] = s; sh[1][wid] = s2; }
    __syncthreads();
    if (wid == 0) {
        float a = (lane < 8) ? sh[0][lane] : 0.0f;
        float c = (lane < 8) ? sh[1][lane] : 0.0f;
        a = warp_sum(a); c = warp_sum(c);
        if (lane == 0) { sh[0][0] = a; sh[1][0] = c; }
    }
    __syncthreads();
    s = sh[0][0]; s2 = sh[1][0];

    float mean = s * (1.0f / (float)CDIM);
    float var  = (s2 - (float)CDIM * mean * mean) * (1.0f / (float)(CDIM - 1));
    float rstd = rsqrtf(var + 1e-5f);

    size_t base = (size_t)row * CDIM;
#pragma unroll
    for (int j = 0; j < 3; j++) {
        int c = t + j * 256;
        float v = (j == 0 ? v0 : (j == 1 ? v1 : v2));
        y[base + c] = __float2half_rn((v - mean) * rstd * w[c] + b[c]);
    }

    if (CVT) {
        int i = blockIdx.x * 256 + t;
        if (i < N4_TOTAL) {
            const float4* src;
            int j = i;
            if (j < N4_QKV) { src = w0; }
            else if ((j -= N4_QKV) < N4_PROJ) { src = w1; }
            else if ((j -= N4_PROJ) < N4_FC) { src = w2; }
            else { j -= N4_FC; src = w3; }
            float4 v = src[j];
            hw[2 * i]     = packh(v.x, v.y);
            hw[2 * i + 1] = packh(v.z, v.w);
        }
    }
}

// ---------------- fp16 tensor-core GEMM, 128x128x32 ----------------
// EPI: 0=+bias, 1=gelu(+bias), 2=+bias+residual.
// SCALEQ: multiply output cols < CDIM by QSCALE (qkv call only).
#define GEMM_SMEM_ELEMS ((2*128*40) + (2*32*136))
#define GEMM_SMEM_BYTES (GEMM_SMEM_ELEMS * 2)

template<int EPI, bool STOREF, bool STOREH, bool SCALEQ>
__global__ __launch_bounds__(256, 2) void hgemm(
    int M, int N, int K,
    const __half* __restrict__ A, const __half* __restrict__ B,
    const float* __restrict__ bias, const float* __restrict__ Res,
    float* __restrict__ C, __half* __restrict__ Ch)
{
    extern __shared__ __half sm[];
    __half* sA = sm;                    // [2][128][40]
    __half* sB = sA + 2 * 128 * 40;     // [2][32][136]
    const uint32_t uA = smem_u32(sA), uB = smem_u32(sB);

    const int tid  = threadIdx.x;
    const int warp = tid >> 5, lane = tid & 31;
    const int wr = warp >> 1, wc = warp & 1;
    const int bm = blockIdx.y * 128, bn = blockIdx.x * 128;

    float acc[2][8][4];
#pragma unroll
    for (int i = 0; i < 2; i++)
#pragma unroll
        for (int j = 0; j < 8; j++)
#pragma unroll
            for (int k = 0; k < 4; k++) acc[i][j][k] = 0.0f;

    auto load_tile = [&](int kt, int buf) {
#pragma unroll
        for (int i = 0; i < 2; i++) {
            int id = tid + i * 256;
            int r = id >> 2, c = id & 3;
            uint32_t off = (uint32_t)((buf * 128 + r) * 40 + c * 8) * 2;
            cp16(uA + off, A + (size_t)(bm + r) * K + kt * 32 + c * 8);
        }
#pragma unroll
        for (int i = 0; i < 2; i++) {
            int id = tid + i * 256;
            int r = id >> 4, c = id & 15;
            uint32_t off = (uint32_t)((buf * 32 + r) * 136 + c * 8) * 2;
            cp16(uB + off, B + (size_t)(kt * 32 + r) * N + bn + c * 8);
        }
    };

    const int KT = K >> 5;
    load_tile(0, 0);
    cp_commit();

    for (int kt = 0; kt < KT; ++kt) {
        const int buf = kt & 1;
        if (kt + 1 < KT) {
            load_tile(kt + 1, buf ^ 1);
            cp_commit();
            cp_wait<1>();
        } else {
            cp_wait<0>();
        }
        __syncthreads();

#pragma unroll
        for (int ks = 0; ks < 2; ++ks) {
            uint32_t a[2][4], b[8][2];
#pragma unroll
            for (int ti = 0; ti < 2; ++ti) {
                int r = wr * 32 + ti * 16 + (lane & 15);
                int col = ks * 16 + (lane >> 4) * 8;
                ldsm_x4(a[ti], uA + (uint32_t)((buf * 128 + r) * 40 + col) * 2);
            }
#pragma unroll
            for (int p = 0; p < 4; ++p) {
                int kr = ks * 16 + (lane & 15);
                int col = wc * 64 + p * 16 + (lane >> 4) * 8;
                uint32_t r4[4];
                ldsm_x4t(r4, uB + (uint32_t)((buf * 32 + kr) * 136 + col) * 2);
                b[2 * p][0] = r4[0]; b[2 * p][1] = r4[1];
                b[2 * p + 1][0] = r4[2]; b[2 * p + 1][1] = r4[3];
            }
#pragma unroll
            for (int ti = 0; ti < 2; ++ti)
#pragma unroll
                for (int nj = 0; nj < 8; ++nj)
                    mma16816(acc[ti][nj], a[ti], b[nj]);
        }
        __syncthreads();
    }

    const int row_base = bm + wr * 32;
    const int col_base = bn + wc * 64;
#pragma unroll
    for (int ti = 0; ti < 2; ++ti) {
        int r0 = row_base + ti * 16 + (lane >> 2);
#pragma unroll
        for (int nj = 0; nj < 8; ++nj) {
            int col = col_base + nj * 8 + (lane & 3) * 2;
            float b0 = bias[col], b1 = bias[col + 1];
            float v00 = acc[ti][nj][0] + b0, v01 = acc[ti][nj][1] + b1;
            float v10 = acc[ti][nj][2] + b0, v11 = acc[ti][nj][3] + b1;
            if (EPI == 1) {
                v00 = gelu_tanh(v00); v01 = gelu_tanh(v01);
                v10 = gelu_tanh(v10); v11 = gelu_tanh(v11);
            }
            if (SCALEQ && col < CDIM) {
                v00 *= QSCALE; v01 *= QSCALE;
                v10 *= QSCALE; v11 *= QSCALE;
            }
            size_t o0 = (size_t)r0 * N + col;
            size_t o1 = (size_t)(r0 + 8) * N + col;
            if (EPI == 2) {
                v00 += Res[o0]; v01 += Res[o0 + 1];
                v10 += Res[o1]; v11 += Res[o1 + 1];
            }
            if (STOREF) {
                float2 f0; f0.x = v00; f0.y = v01;
                float2 f1; f1.x = v10; f1.y = v11;
                *(float2*)(C + o0) = f0;
                *(float2*)(C + o1) = f1;
            }
            if (STOREH) {
                *(uint32_t*)(Ch + o0) = packh(v00, v01);
                *(uint32_t*)(Ch + o1) = packh(v10, v11);
            }
        }
    }
}

// ---------------- Flash attention, fp16 tensor cores (best config) ---
// Br=128 (8 warps), Bc=64. 4-stage KV ring, 1 barrier per 2 tiles.
// Q pre-scaled by QSCALE. O-rescale skipped (warp-uniform branch) when
// no row in the warp updated its running max (alpha == 1 exactly).
#define FAP 72
#define FA_Q_ELEMS (128 * FAP)
#define FA_KV_ELEMS (64 * FAP)
#define FA2_SMEM ((FA_Q_ELEMS + 8 * FA_KV_ELEMS) * 2)

__global__ __launch_bounds__(256, 2) void flash_attn_tc(
    const __half* __restrict__ qkv, __half* __restrict__ outp)
{
    extern __shared__ __half sb[];
    __half* sQ = sb;                       // [128][72]
    __half* sKV = sQ + FA_Q_ELEMS;         // [4][K,V][64][72]

    const int tid = threadIdx.x, lane = tid & 31, w = tid >> 5;
    const int b = blockIdx.z, h = blockIdx.y;
    const int qtb = (gridDim.x - 1) - blockIdx.x;   // heavy tiles first
    const int q0 = qtb * 128;
    const size_t rs = 3 * CDIM;
    const __half* base = qkv + (size_t)b * TSEQ * rs + h * HD;

    auto loadKV = [&](int kt) {
        const int k0 = kt * 64;
        __half* d = sKV + (kt & 3) * 2 * FA_KV_ELEMS;
        const __half* srcs[2] = { base + CDIM, base + 2 * CDIM };
#pragma unroll
        for (int a = 0; a < 2; a++) {
#pragma unroll
            for (int i = 0; i < 2; i++) {
                int id = tid + i * 256;
                int r = id >> 3, c8 = id & 7;
                cp16(smem_u32(d + a * FA_KV_ELEMS + r * FAP + c8 * 8),
                     srcs[a] + (size_t)(k0 + r) * rs + c8 * 8);
            }
        }
    };

#pragma unroll
    for (int i = 0; i < 4; i++) {
        int id = tid + i * 256;
        int r = id >> 3, c8 = id & 7;
        cp16(smem_u32(sQ + r * FAP + c8 * 8), base + (size_t)(q0 + r) * rs + c8 * 8);
    }
    loadKV(0);
    loadKV(1);
    cp_commit();

    float o[8][4];
#pragma unroll
    for (int nt = 0; nt < 8; nt++)
#pragma unroll
        for (int e = 0; e < 4; e++) o[nt][e] = 0.0f;
    float m[2] = {-1e30f, -1e30f}, l[2] = {0.0f, 0.0f};
    uint32_t qf[4][4];

    const int NT = 2 * qtb + 2;
    const int rmin = q0 + w * 16;
    const int rmax = rmin + 15;

    for (int kt0 = 0; kt0 < NT; kt0 += 2) {
        cp_wait<0>();
        __syncthreads();
        if (kt0 + 2 < NT) {
            loadKV(kt0 + 2);
            loadKV(kt0 + 3);
            cp_commit();
        }
        if (kt0 == 0) {
#pragma unroll
            for (int ks = 0; ks < 4; ks++) {
                uint32_t off = (uint32_t)((w * 16 + (lane & 15)) * FAP
                                          + ks * 16 + (lane >> 4) * 8) * 2;
                ldsm_x4(qf[ks], smem_u32(sQ) + off);
            }
        }

#pragma unroll
        for (int sub = 0; sub < 2; sub++) {
            const int kt = kt0 + sub;
            const int k0 = kt * 64;
            if (k0 > rmax) continue;
            __half* Kt = sKV + (kt & 3) * 2 * FA_KV_ELEMS;
            __half* Vt = Kt + FA_KV_ELEMS;

            float s[8][4];
#pragma unroll
            for (int nt = 0; nt < 8; nt++)
#pragma unroll
                for (int e = 0; e < 4; e++) s[nt][e] = 0.0f;

            // S = Q K^T  (log2 domain via pre-scaled Q)
#pragma unroll
            for (int ks = 0; ks < 4; ks++) {
                uint32_t kb[8][2];
#pragma unroll
                for (int p = 0; p < 4; p++) {
                    uint32_t roff = (uint32_t)((p * 16 + ((lane >> 4) << 3) + (lane & 7)) * FAP
                                               + ks * 16 + (((lane >> 3) & 1) << 3)) * 2;
                    uint32_t r4[4];
                    ldsm_x4(r4, smem_u32(Kt) + roff);
                    kb[2 * p][0] = r4[0]; kb[2 * p][1] = r4[1];
                    kb[2 * p + 1][0] = r4[2]; kb[2 * p + 1][1] = r4[3];
                }
#pragma unroll
                for (int t = 0; t < 8; t++) mma16816(s[t], qf[ks], kb[t]);
            }

            if (k0 + 63 > rmin) {
#pragma unroll
                for (int nt = 0; nt < 8; nt++)
#pragma unroll
                    for (int e = 0; e < 4; e++) {
                        int col = k0 + nt * 8 + 2 * (lane & 3) + (e & 1);
                        int rr = rmin + (lane >> 2) + (e >> 1) * 8;
                        if (col > rr) s[nt][e] = -1e30f;
                    }
            }

            // online softmax; skip O-rescale when warp saw no max update
            bool upd = false;
            float alpha_[2];
#pragma unroll
            for (int half = 0; half < 2; half++) {
                float tm = -1e30f;
#pragma unroll
                for (int nt = 0; nt < 8; nt++)
                    tm = fmaxf(tm, fmaxf(s[nt][2 * half], s[nt][2 * half + 1]));
                tm = fmaxf(tm, __shfl_xor_sync(0xffffffffu, tm, 1));
                tm = fmaxf(tm, __shfl_xor_sync(0xffffffffu, tm, 2));
                float mold = m[half];
                float mn = fmaxf(mold, tm);
                upd |= (tm > mold);
                alpha_[half] = fast_ex2(mold - mn);
                m[half] = mn;
                float ps = 0.0f;
#pragma unroll
                for (int nt = 0; nt < 8; nt++) {
                    s[nt][2 * half]     = fast_ex2(s[nt][2 * half] - mn);
                    s[nt][2 * half + 1] = fast_ex2(s[nt][2 * half + 1] - mn);
                    ps += s[nt][2 * half] + s[nt][2 * half + 1];
                }
                l[half] = l[half] * alpha_[half] + ps;
            }
            if (__any_sync(0xffffffffu, upd)) {
#pragma unroll
                for (int half = 0; half < 2; half++)
#pragma unroll
                    for (int nt = 0; nt < 8; nt++) {
                        o[nt][2 * half]     *= alpha_[half];
                        o[nt][2 * half + 1] *= alpha_[half];
                    }
            }

            // O += P V
#pragma unroll
            for (int ks = 0; ks < 4; ks++) {
                uint32_t pa[4];
                pa[0] = packh(s[2 * ks][0],     s[2 * ks][1]);
                pa[1] = packh(s[2 * ks][2],     s[2 * ks][3]);
                pa[2] = packh(s[2 * ks + 1][0], s[2 * ks + 1][1]);
                pa[3] = packh(s[2 * ks + 1][2], s[2 * ks + 1][3]);
                uint32_t vb[8][2];
#pragma unroll
                for (int p = 0; p < 4; p++) {
                    uint32_t roff = (uint32_t)((ks * 16 + (lane & 15)) * FAP
                                               + p * 16 + (lane >> 4) * 8) * 2;
                    uint32_t r4[4];
                    ldsm_x4t(r4, smem_u32(Vt) + roff);
                    vb[2 * p][0] = r4[0]; vb[2 * p][1] = r4[1];
                    vb[2 * p + 1][0] = r4[2]; vb[2 * p + 1][1] = r4[3];
                }
#pragma unroll
                for (int t = 0; t < 8; t++) mma16816(o[t], pa, vb[t]);
            }
        }
    }

    float linv[2];
#pragma unroll
    for (int half = 0; half < 2; half++) {
        float lv = l[half];
        lv += __shfl_xor_sync(0xffffffffu, lv, 1);
        lv += __shfl_xor_sync(0xffffffffu, lv, 2);
        linv[half] = 1.0f / lv;
    }
#pragma unroll
    for (int nt = 0; nt < 8; nt++) {
#pragma unroll
        for (int half = 0; half < 2; half++) {
            int rowg = q0 + w * 16 + (lane >> 2) + half * 8;
            int colg = h * HD + nt * 8 + 2 * (lane & 3);
            float f0 = o[nt][2 * half]     * linv[half];
            float f1 = o[nt][2 * half + 1] * linv[half];
            size_t off = (size_t)(b * TSEQ + rowg) * CDIM + colg;
            *(uint32_t*)(outp + off) = packh(f0, f1);
        }
    }
}

// ---------------- launch ----------------
extern "C" void kernel_launch(void* const* d_in, const int* in_sizes, int n_in,
                              void* d_out, int out_size)
{
    const float* x       = (const float*)d_in[0];
    const float* ln1_w   = (const float*)d_in[1];
    const float* ln1_b   = (const float*)d_in[2];
    const float* attn_w  = (const float*)d_in[3];
    const float* attn_b  = (const float*)d_in[4];
    const float* proj_w  = (const float*)d_in[5];
    const float* proj_b  = (const float*)d_in[6];
    const float* ln2_w   = (const float*)d_in[7];
    const float* ln2_b   = (const float*)d_in[8];
    const float* fc_w    = (const float*)d_in[9];
    const float* fc_b    = (const float*)d_in[10];
    const float* mproj_w = (const float*)d_in[11];
    const float* mproj_b = (const float*)d_in[12];
    float* out = (float*)d_out;

    __half *ln, *qkv, *att, *fc, *wv;
    float *x1;
    cudaGetSymbolAddress((void**)&ln,  g_ln);
    cudaGetSymbolAddress((void**)&qkv, g_qkv);
    cudaGetSymbolAddress((void**)&att, g_att);
    cudaGetSymbolAddress((void**)&x1,  g_x1);
    cudaGetSymbolAddress((void**)&fc,  g_fc);
    cudaGetSymbolAddress((void**)&wv,  g_w);

    __half *wqkv = wv;
    __half *wproj = wv + W_QKV_N;
    __half *wfc = wproj + W_PROJ_N;
    __half *wmp = wfc + W_FC_N;

    cudaFuncSetAttribute(flash_attn_tc,
                         cudaFuncAttributeMaxDynamicSharedMemorySize, FA2_SMEM);
    cudaFuncSetAttribute((const void*)hgemm<0, false, true, true>,
                         cudaFuncAttributeMaxDynamicSharedMemorySize, GEMM_SMEM_BYTES);
    cudaFuncSetAttribute((const void*)hgemm<2, true, false, false>,
                         cudaFuncAttributeMaxDynamicSharedMemorySize, GEMM_SMEM_BYTES);
    cudaFuncSetAttribute((const void*)hgemm<1, false, true, false>,
                         cudaFuncAttributeMaxDynamicSharedMemorySize, GEMM_SMEM_BYTES);

    // 1) ln1 -> fp16, fused with full weight conversion (one launch)
    ln_kernel<true><<<MROWS, 256>>>(
        x, ln1_w, ln1_b, ln,
        (const float4*)attn_w, (const float4*)proj_w,
        (const float4*)fc_w, (const float4*)mproj_w, (uint32_t*)wv);
    // 2) qkv = ln1 @ W_attn + b (q cols pre-scaled by QSCALE) -> fp16
    hgemm<0, false, true, true><<<dim3(2304 / 128, MROWS / 128), 256, GEMM_SMEM_BYTES>>>(
        MROWS, 2304, CDIM, ln, wqkv, attn_b, nullptr, nullptr, qkv);
    // 3) attention -> fp16
    flash_attn_tc<<<dim3(TSEQ / 128, NHEAD, NBATCH), 256, FA2_SMEM>>>(qkv, att);
    // 4) x1 = x + att @ W_proj + b   (fp32)
    hgemm<2, true, false, false><<<dim3(CDIM / 128, MROWS / 128), 256, GEMM_SMEM_BYTES>>>(
        MROWS, CDIM, CDIM, att, wproj, proj_b, x, x1, nullptr);
    // 5) ln2 -> fp16 (plain)
    ln_kernel<false><<<MROWS, 256>>>(
        x1, ln2_w, ln2_b, ln, nullptr, nullptr, nullptr, nullptr, nullptr);
    // 6) fc = gelu(ln2 @ W_fc + b)   [8192, 3072] -> fp16
    hgemm<1, false, true, false><<<dim3(3072 / 128, MROWS / 128), 256, GEMM_SMEM_BYTES>>>(
        MROWS, 3072, CDIM, ln, wfc, fc_b, nullptr, nullptr, fc);
    // 7) out = x1 + fc @ W_mproj + b   (fp32)
    hgemm<2, true, false, false><<<dim3(CDIM / 128, MROWS / 128), 256, GEMM_SMEM_BYTES>>>(
        MROWS, CDIM, 4 * CDIM, fc, wmp, mproj_b, x1, out, nullptr);
}